// round 8
// baseline (speedup 1.0000x reference)
#include <cuda_runtime.h>
#include <cstdint>

// Problem constants (fixed by the reference)
#define B_ 32
#define S_ 512
#define P_ 8
#define K_ 256
#define D_ 64
#define NROWS (B_ * S_ * P_)   // 131072 rows of K=256 logits each

#define FULL 0xffffffffu
#define NEG_INF __int_as_float(0xff800000)
#define LN2F 0.69314718055994530942f

// Rotation multipliers 2^r, loaded at RUNTIME so ptxas cannot strength-reduce
// the muls back into SHF. Used to move 11 of the 20 threefry rotates onto the
// fma pipe (mul.lo + mul.hi), balancing alu vs fma pipe load.
__device__ uint32_t d_rotmul[8] = {
    1u << 13, 1u << 15, 1u << 26, 1u << 17, 1u << 16, 0u, 0u, 0u
};

struct RotM { uint32_t m13, m15, m26, m17, m16; };

__device__ __forceinline__ uint32_t rotl32(uint32_t x, int r) {
    return __funnelshift_l(x, x, r);
}
// rotl via two 32-bit muls on the fma pipe: lo = x<<r, hi = x>>(32-r) (disjoint)
__device__ __forceinline__ uint32_t mulrot(uint32_t x, uint32_t mul) {
    uint32_t lo, hi;
    asm("mul.lo.u32 %0, %1, %2;" : "=r"(lo) : "r"(x), "r"(mul));
    asm("mul.hi.u32 %0, %1, %2;" : "=r"(hi) : "r"(x), "r"(mul));
    return lo | hi;   // folds with the following ^x0 into one LOP3
}
__device__ __forceinline__ float lg2a(float x) {
    float r;
    asm("lg2.approx.f32 %0, %1;" : "=f"(r) : "f"(x));
    return r;
}

// ---------------------------------------------------------------------------
// JAX threefry2x32, partitionable mode, key (0, 42); counter = (0, i).
// Draw = x0 ^ x1. ks = (0, 42, 0x1BD11BDA^42).
// 11 rounds use the fma-pipe rotate (RM), 9 use the alu-pipe funnel shift (RS).
// ---------------------------------------------------------------------------
__device__ __forceinline__ uint32_t threefry_bits(uint32_t i, const RotM& R) {
    const uint32_t KS1 = 42u;
    const uint32_t KS2 = 0x1BD11BDAu ^ 42u;
#define RM(mul) { x0 += x1; x1 = mulrot(x1, (mul)) ^ x0; }
#define RS(r)   { x0 += x1; x1 = rotl32(x1, (r)) ^ x0; }
    uint32_t x1 = i + KS1;
    uint32_t x0 = x1;                        // round 1 add: x0 = 0 + x1
    x1 = mulrot(x1, R.m13) ^ x0;             // R1  (mul)
    RM(R.m15)                                 // R2  (mul)
    RM(R.m26)                                 // R3  (mul)
    RS(6)                                     // R4
    x0 += KS1;  x1 += KS2 + 1u;
    RM(R.m17)  RS(29)  RM(R.m16)  RS(24)      // R5-R8
    x0 += KS2;  x1 += 2u;                     // ks0 = 0
    RM(R.m13)  RS(15)  RM(R.m26)  RS(6)       // R9-R12
    /* x0 += ks0 == 0 */ x1 += KS1 + 3u;
    RM(R.m17)  RS(29)  RM(R.m16)  RS(24)      // R13-R16
    x0 += KS1;  x1 += KS2 + 4u;
    RM(R.m13)  RS(15)  RM(R.m26)  RS(6)       // R17-R20
    x0 += KS2;  x1 += 5u;
#undef RM
#undef RS
    return x0 ^ x1;
}

// Exact path: bit-identical to the reference fp32 computation (accurate logf).
__device__ __forceinline__ float exact_score(const float* __restrict__ erow,
                                             uint32_t row_base, int k,
                                             const RotM& R) {
    uint32_t bits = threefry_bits(row_base + (uint32_t)k, R);
    float f = __uint_as_float((bits >> 9) | 0x3f800000u) - 1.0f;  // u in [0,1)
    float u = fmaxf(f, 1.17549435e-38f);
    float g = -logf(-logf(u));
    return __ldg(erow + k) + g;
}

// ---------------------------------------------------------------------------
// One warp per (b, s, p) row. Fast scores via lg2.approx (MUFU pipe):
//   s_j = e_j - ln2 * lg2(-lg2(u_j)*ln2),  |s_j - exact_j| <= ~2.5e-5.
// If exactly ONE element has s_j >= smax - 4e-4, it is provably the reference
// argmax. Else (~50 rows in 131072) rerun the bit-exact accurate-logf path on
// the candidate band with first-index tie-break.
// ---------------------------------------------------------------------------
__global__ void __launch_bounds__(256, 8) symbolic_gumbel_kernel(
    const int*   __restrict__ inputs,       // [B, S] int32
    const float* __restrict__ pattern_map,  // [N_CAT, P, K]
    const float* __restrict__ symbols,      // [K, D]
    float*       __restrict__ out)          // [B, S, P*D]
{
    const int warp = (blockIdx.x * blockDim.x + threadIdx.x) >> 5;
    const int lane = threadIdx.x & 31;

    // Rotation multipliers: uniform, loaded once (candidates for UR promotion).
    RotM R;
    {
        uint4 a = *reinterpret_cast<const uint4*>(&d_rotmul[0]);
        R.m13 = a.x; R.m15 = a.y; R.m26 = a.z; R.m17 = a.w;
        R.m16 = d_rotmul[4];
    }

    const int row = warp;                    // grid covers exactly NROWS warps
    const int bs  = row >> 3;
    const int p   = row & 7;
    const int cat = __ldg(&inputs[bs]);

    const float* erow = pattern_map + ((size_t)cat * P_ + p) * K_;
    const uint32_t row_base = (uint32_t)row * (uint32_t)K_;
    const uint32_t base = row_base + (uint32_t)(lane * 8);

    const float4* e4 = reinterpret_cast<const float4*>(erow + lane * 8);
    float4 ea = __ldg(&e4[0]);
    float4 eb = __ldg(&e4[1]);
    float e[8] = {ea.x, ea.y, ea.z, ea.w, eb.x, eb.y, eb.z, eb.w};

    // ---- Pass 1: fast scores, max only ----
    float s[8];
    float smax = NEG_INF;
#pragma unroll
    for (int j = 0; j < 8; j++) {
        uint32_t bits = threefry_bits(base + (uint32_t)j, R);
        float f  = __uint_as_float((bits >> 9) | 0x3f800000u) - 1.0f;  // u in [0,1)
        float u  = fmaxf(f, 1.17549435e-38f);
        float yl = lg2a(u) * (-LN2F);            // = -ln(u) > 0
        float x  = fmaf(lg2a(yl), -LN2F, e[j]);  // e_j - ln(-ln u)
        s[j] = x;
        smax = fmaxf(smax, x);
    }
#pragma unroll
    for (int off = 16; off > 0; off >>= 1)
        smax = fmaxf(smax, __shfl_xor_sync(FULL, smax, off));

    // ---- Candidate band ----
    const float thr = smax - 4e-4f;
    int cnt = 0, jm = 8;
#pragma unroll
    for (int j = 0; j < 8; j++) {
        bool c = (s[j] >= thr);
        cnt += c;
        if (c && jm == 8) jm = j;
    }
    const int tot = __reduce_add_sync(FULL, cnt);

    int bestk;
    if (tot == 1) {
        // Unique candidate == reference argmax (error band is provable).
        unsigned ball = __ballot_sync(FULL, cnt > 0);
        int owner = __ffs(ball) - 1;
        bestk = __shfl_sync(FULL, lane * 8 + jm, owner);
    } else {
        // Rare: exact (reference-identical) scores on the candidate band.
        float bestx = NEG_INF;
        bestk = K_;
#pragma unroll
        for (int j = 0; j < 8; j++) {
            bool cand = (s[j] >= thr);
            if (__any_sync(FULL, cand)) {
                int   k = lane * 8 + j;
                float x = NEG_INF;
                if (cand) x = exact_score(erow, row_base, k, R);
                if (x > bestx || (x == bestx && k < bestk)) { bestx = x; bestk = k; }
            }
        }
#pragma unroll
        for (int off = 16; off > 0; off >>= 1) {
            float ob = __shfl_xor_sync(FULL, bestx, off);
            int   ok = __shfl_xor_sync(FULL, bestk, off);
            if (ob > bestx || (ob == bestx && ok < bestk)) { bestx = ob; bestk = ok; }
        }
    }

    // Copy symbols[bestk, :] (64 floats = 256B) to out[row, :], 2 floats/lane
    const float2* srow = reinterpret_cast<const float2*>(symbols + (size_t)bestk * D_);
    float2 val = __ldg(&srow[lane]);
    float2* orow = reinterpret_cast<float2*>(out + (size_t)row * D_);
    orow[lane] = val;
}

extern "C" void kernel_launch(void* const* d_in, const int* in_sizes, int n_in,
                              void* d_out, int out_size) {
    const int*   inputs      = (const int*)  d_in[0];  // [32, 512] int32
    const float* pattern_map = (const float*)d_in[1];  // [50000, 8, 256]
    const float* symbols     = (const float*)d_in[2];  // [256, 64]
    // d_in[3] = tau (== 1.0, positive): argmax invariant; straight-through
    // weights are one-hot to fp32 rounding, so tau is unused.
    float* out = (float*)d_out;                        // [32, 512, 512]

    const int threads = 256;                 // 8 warps -> 8 rows per block
    const int blocks  = NROWS / 8;           // 16384
    symbolic_gumbel_kernel<<<blocks, threads>>>(inputs, pattern_map, symbols, out);
}

// round 9
// speedup vs baseline: 1.1589x; 1.1589x over previous
#include <cuda_runtime.h>
#include <cstdint>

// Problem constants (fixed by the reference)
#define B_ 32
#define S_ 512
#define P_ 8
#define K_ 256
#define D_ 64
#define NROWS (B_ * S_ * P_)   // 131072 rows of K=256 logits each

#define FULL 0xffffffffu
#define NEG_INF __int_as_float(0xff800000)
#define LN2F 0.69314718055994530942f
#define TINYF 1.17549435e-38f

__device__ __forceinline__ uint32_t rotl32(uint32_t x, int r) {
    return __funnelshift_l(x, x, r);
}
__device__ __forceinline__ float lg2a(float x) {
    float r;
    asm("lg2.approx.f32 %0, %1;" : "=f"(r) : "f"(x));
    return r;
}

// ---------------------------------------------------------------------------
// JAX threefry2x32, partitionable mode, key (0, 42); counter = (0, i).
// Draw = x0 ^ x1. ks = (0, 42, 0x1BD11BDA^42). Plain SHF/LOP3/IADD core —
// R5/R8 proved any pipe-relocation of the core loses on issue slots.
// ---------------------------------------------------------------------------
__device__ __forceinline__ uint32_t threefry_bits(uint32_t i) {
    const uint32_t KS1 = 42u;
    const uint32_t KS2 = 0x1BD11BDAu ^ 42u;
    uint32_t x1 = i + KS1;
    uint32_t x0 = x1;                  // round 1: x0 = 0 + x1
    x1 = rotl32(x1, 13) ^ x0;
#define RND(r) { x0 += x1; x1 = rotl32(x1, (r)) ^ x0; }
    RND(15) RND(26) RND(6)
    x0 += KS1;  x1 += KS2 + 1u;
    RND(17) RND(29) RND(16) RND(24)
    x0 += KS2;  x1 += 2u;              // ks0 = 0
    RND(13) RND(15) RND(26) RND(6)
    /* x0 += ks0 == 0 */ x1 += KS1 + 3u;
    RND(17) RND(29) RND(16) RND(24)
    x0 += KS1;  x1 += KS2 + 4u;
    RND(13) RND(15) RND(26) RND(6)
    x0 += KS2;  x1 += 5u;
#undef RND
    return x0 ^ x1;
}

// Exact path: bit-identical to the reference fp32 computation (accurate logf).
// (f + TINYF == fmaxf(f, tiny) for every representable f in {0} U [2^-23, 1).)
__device__ __forceinline__ float exact_score(const float* __restrict__ erow,
                                             uint32_t row_base, int k) {
    uint32_t bits = threefry_bits(row_base + (uint32_t)k);
    float f = __uint_as_float((bits >> 9) | 0x3f800000u) - 1.0f;  // u in [0,1)
    float u = f + TINYF;
    float g = -logf(-logf(u));
    return __ldg(erow + k) + g;
}

// ---------------------------------------------------------------------------
// One warp per (b, s, p) row. Fast scores via lg2.approx (MUFU pipe):
//   s_j = e_j - ln2 * lg2a(-lg2a(u_j))  ==  (exact_j - ln(ln 2)-shift) +- ~2.5e-5
// The uniform per-row shift cancels in all band comparisons. If exactly ONE
// element has s_j >= smax - 4e-4 it is the reference argmax; else (~50 rows
// in 131072) rerun the bit-exact accurate-logf path on the candidate band.
// ---------------------------------------------------------------------------
__global__ void __launch_bounds__(256, 8) symbolic_gumbel_kernel(
    const int*   __restrict__ inputs,       // [B, S] int32
    const float* __restrict__ pattern_map,  // [N_CAT, P, K]
    const float* __restrict__ symbols,      // [K, D]
    float*       __restrict__ out)          // [B, S, P*D]
{
    const int warp = (blockIdx.x * blockDim.x + threadIdx.x) >> 5;
    const int lane = threadIdx.x & 31;

    const int row = warp;                    // grid covers exactly NROWS warps
    const int bs  = row >> 3;
    const int p   = row & 7;
    const int cat = __ldg(&inputs[bs]);

    const float* erow = pattern_map + ((size_t)cat * P_ + p) * K_;
    const uint32_t row_base = (uint32_t)row * (uint32_t)K_;
    const uint32_t base = row_base + (uint32_t)(lane * 8);

    const float4* e4 = reinterpret_cast<const float4*>(erow + lane * 8);
    float4 ea = __ldg(&e4[0]);
    float4 eb = __ldg(&e4[1]);
    float e[8] = {ea.x, ea.y, ea.z, ea.w, eb.x, eb.y, eb.z, eb.w};

    // ---- Pass 1: fast scores ----
    float s[8];
#pragma unroll
    for (int j = 0; j < 8; j++) {
        uint32_t bits = threefry_bits(base + (uint32_t)j);
        float f  = __uint_as_float((bits >> 9) | 0x3f800000u) - 1.0f;  // u in [0,1)
        float u  = f + TINYF;               // == fmaxf(f, tiny), on the fma pipe
        float l1 = lg2a(u);                 // < 0
        float t  = lg2a(-l1);               // neg folds into MUFU src modifier
        s[j] = fmaf(t, -LN2F, e[j]);        // e - ln2*lg2(-lg2 u)
    }

    // Lane-local max (tree) then warp REDUX via monotone uint mapping.
    float m0 = fmaxf(s[0], s[1]), m1 = fmaxf(s[2], s[3]);
    float m2 = fmaxf(s[4], s[5]), m3 = fmaxf(s[6], s[7]);
    float lmax = fmaxf(fmaxf(m0, m1), fmaxf(m2, m3));
    uint32_t ub = __float_as_uint(lmax);
    ub ^= (uint32_t)((int32_t)ub >> 31) | 0x80000000u;     // order-preserving map
    uint32_t um = __reduce_max_sync(FULL, ub);
    um ^= ~(uint32_t)((int32_t)um >> 31) | 0x80000000u;    // inverse map
    const float smax = __uint_as_float(um);

    // ---- Candidate band as a bitmask ----
    const float thr = smax - 4e-4f;
    uint32_t mask = 0;
#pragma unroll
    for (int j = 0; j < 8; j++)
        if (s[j] >= thr) mask |= (1u << j);
    const int tot = __reduce_add_sync(FULL, __popc(mask));

    int bestk;
    if (tot == 1) {
        // Unique candidate == reference argmax (error band is provable).
        unsigned ball = __ballot_sync(FULL, mask != 0);
        int owner = __ffs(ball) - 1;
        int jm = __ffs(mask) - 1;            // valid on owner lane
        bestk = __shfl_sync(FULL, lane * 8 + jm, owner);
    } else {
        // Rare: exact (reference-identical) scores on the candidate band.
        float bestx = NEG_INF;
        bestk = K_;
#pragma unroll
        for (int j = 0; j < 8; j++) {
            bool cand = (mask >> j) & 1u;
            if (__any_sync(FULL, cand)) {
                int   k = lane * 8 + j;
                float x = NEG_INF;
                if (cand) x = exact_score(erow, row_base, k);
                if (x > bestx || (x == bestx && k < bestk)) { bestx = x; bestk = k; }
            }
        }
#pragma unroll
        for (int off = 16; off > 0; off >>= 1) {
            float ob = __shfl_xor_sync(FULL, bestx, off);
            int   ok = __shfl_xor_sync(FULL, bestk, off);
            if (ob > bestx || (ob == bestx && ok < bestk)) { bestx = ob; bestk = ok; }
        }
    }

    // Copy symbols[bestk, :] (64 floats = 256B) to out[row, :], 2 floats/lane
    const float2* srow = reinterpret_cast<const float2*>(symbols + (size_t)bestk * D_);
    float2 val = __ldg(&srow[lane]);
    float2* orow = reinterpret_cast<float2*>(out + (size_t)row * D_);
    orow[lane] = val;
}

extern "C" void kernel_launch(void* const* d_in, const int* in_sizes, int n_in,
                              void* d_out, int out_size) {
    const int*   inputs      = (const int*)  d_in[0];  // [32, 512] int32
    const float* pattern_map = (const float*)d_in[1];  // [50000, 8, 256]
    const float* symbols     = (const float*)d_in[2];  // [256, 64]
    // d_in[3] = tau (== 1.0, positive): argmax invariant; straight-through
    // weights are one-hot to fp32 rounding, so tau is unused.
    float* out = (float*)d_out;                        // [32, 512, 512]

    const int threads = 256;                 // 8 warps -> 8 rows per block
    const int blocks  = NROWS / 8;           // 16384
    symbolic_gumbel_kernel<<<blocks, threads>>>(inputs, pattern_map, symbols, out);
}